// round 1
// baseline (speedup 1.0000x reference)
#include <cuda_runtime.h>
#include <math.h>

// Problem constants
#define MDIM 384
#define LDIM 25
#define NIMG 64
#define HIMG 28
#define FHW  5
#define OHDIM 24
#define PDIM 576          // 24*24
#define NPROWS (PDIM*NIMG)  // 36864
#define JITTER_F 1e-6f

// ---------------- device scratch (static allocations allowed) ----------------
__device__ float g_Zs[MDIM*LDIM];        // Z / lengthscale
__device__ float g_Zsq[MDIM];            // row norms^2 of Zs
__device__ float g_Xs[NIMG*HIMG*HIMG];   // X / lengthscale
__device__ float g_Kuu[MDIM*MDIM];
__device__ float g_W[MDIM*MDIM];
__device__ float g_W2[MDIM*MDIM];
__device__ float g_R[MDIM*MDIM];
__device__ float g_Ls[MDIM*MDIM];
__device__ float g_qS[MDIM*MDIM];
__device__ float g_T[MDIM*MDIM];
__device__ float g_Cm[MDIM*MDIM];
__device__ float g_alpha[MDIM];
__device__ float g_K[(size_t)NPROWS*MDIM];   // 56.6 MB patch-kernel matrix

// ---------------- prep: scale inputs, tril(q_sqrt), init Newton X0 ----------------
__global__ void prep_kernel(const float* __restrict__ X, const float* __restrict__ Z,
                            const float* __restrict__ qsqrt,
                            const float* __restrict__ pvar, const float* __restrict__ plen) {
    float inv_l = 1.0f / plen[0];
    float w0 = 1.0f / (pvar[0] + JITTER_F);
    int stride = gridDim.x * blockDim.x;
    int tid = blockIdx.x * blockDim.x + threadIdx.x;
    for (int i = tid; i < NIMG*HIMG*HIMG; i += stride) g_Xs[i] = X[i] * inv_l;
    for (int i = tid; i < MDIM*LDIM; i += stride)      g_Zs[i] = Z[i] * inv_l;
    for (int i = tid; i < MDIM*MDIM; i += stride) {
        int r = i / MDIM, c = i - r * MDIM;
        g_Ls[i] = (c <= r) ? qsqrt[i] : 0.0f;
        g_W[i]  = (r == c) ? w0 : 0.0f;
    }
}

__global__ void zsq_kernel() {
    int m = blockIdx.x * blockDim.x + threadIdx.x;
    if (m < MDIM) {
        float s = 0.0f;
        #pragma unroll
        for (int l = 0; l < LDIM; l++) { float z = g_Zs[m*LDIM + l]; s += z*z; }
        g_Zsq[m] = s;
    }
}

// ---------------- Kuu ----------------
__global__ void kuu_kernel(const float* __restrict__ pvar) {
    int idx = blockIdx.x * blockDim.x + threadIdx.x;
    if (idx >= MDIM*MDIM) return;
    int i = idx / MDIM, j = idx - i*MDIM;
    float dot = 0.0f;
    #pragma unroll
    for (int l = 0; l < LDIM; l++) dot += g_Zs[i*LDIM + l] * g_Zs[j*LDIM + l];
    float d2 = g_Zsq[i] + g_Zsq[j] - 2.0f*dot;
    d2 = fmaxf(d2, 0.0f);
    float v = pvar[0] * expf(-0.5f * d2);
    if (i == j) v += JITTER_F;
    g_Kuu[idx] = v;
}

// ---------------- generic 384x384 GEMM ----------------
// mode 0: C = A*B ; mode 1: C = 2I - A*B ; mode 2: C = A*B - D
// transB: use B^T instead of B
__global__ __launch_bounds__(256) void gemm384(const float* __restrict__ A,
                                               const float* __restrict__ B,
                                               float* __restrict__ C,
                                               const float* __restrict__ D,
                                               int mode, int transB) {
    __shared__ float As[32][33];
    __shared__ float Bs[32][33];
    int tid = threadIdx.x;
    int brow = blockIdx.y * 32;
    int bcol = blockIdx.x * 32;
    int lr = tid >> 5;        // 0..7
    int lc = tid & 31;        // 0..31
    int ty = tid >> 4;        // 0..15
    int tx = tid & 15;        // 0..15
    float acc00 = 0.f, acc01 = 0.f, acc10 = 0.f, acc11 = 0.f;

    for (int kt = 0; kt < MDIM; kt += 32) {
        #pragma unroll
        for (int l = 0; l < 4; l++) {
            int r = lr + l*8;
            As[r][lc] = A[(brow + r)*MDIM + kt + lc];
            if (!transB) {
                Bs[r][lc] = B[(kt + r)*MDIM + bcol + lc];
            } else {
                // Bs[k][j] = B[(bcol+j)*M + kt+k]; thread: j = r, k = lc
                Bs[lc][r] = B[(bcol + r)*MDIM + kt + lc];
            }
        }
        __syncthreads();
        #pragma unroll
        for (int k = 0; k < 32; k++) {
            float a0 = As[2*ty][k],   a1 = As[2*ty+1][k];
            float b0 = Bs[k][2*tx],   b1 = Bs[k][2*tx+1];
            acc00 += a0*b0; acc01 += a0*b1;
            acc10 += a1*b0; acc11 += a1*b1;
        }
        __syncthreads();
    }
    int r0 = brow + 2*ty, c0 = bcol + 2*tx;
    float o[2][2] = {{acc00, acc01}, {acc10, acc11}};
    #pragma unroll
    for (int r = 0; r < 2; r++) {
        #pragma unroll
        for (int c = 0; c < 2; c++) {
            int gi = (r0 + r)*MDIM + (c0 + c);
            float v = o[r][c];
            if (mode == 1)      v = ((r0 + r) == (c0 + c) ? 2.0f : 0.0f) - v;
            else if (mode == 2) v = v - D[gi];
            C[gi] = v;
        }
    }
}

// ---------------- alpha = W * q_mu ----------------
__global__ void alpha_kernel(const float* __restrict__ Wf, const float* __restrict__ qmu) {
    int i = blockIdx.x * blockDim.x + threadIdx.x;
    if (i < MDIM) {
        float s = 0.0f;
        for (int j = 0; j < MDIM; j++) s += Wf[i*MDIM + j] * qmu[j];
        g_alpha[i] = s;
    }
}

// ---------------- Kuf + mean ----------------
// block = (oh in x, n in y), 384 threads (one per inducing point m)
__global__ __launch_bounds__(384) void kuf_kernel(const float* __restrict__ pvar,
                                                  float* __restrict__ out_mean) {
    __shared__ float sZ[MDIM*LDIM];
    __shared__ float szsq[MDIM];
    __shared__ float salpha[MDIM];
    __shared__ float simg[FHW*HIMG];
    __shared__ float spsq[OHDIM];
    __shared__ float smean[OHDIM];

    int oh = blockIdx.x;
    int n  = blockIdx.y;
    int m  = threadIdx.x;

    for (int i = m; i < MDIM*LDIM; i += 384) sZ[i] = g_Zs[i];
    szsq[m] = g_Zsq[m];
    salpha[m] = g_alpha[m];
    if (m < FHW*HIMG) {
        int fh = m / HIMG, col = m - fh*HIMG;
        simg[m] = g_Xs[n*(HIMG*HIMG) + (oh + fh)*HIMG + col];
    }
    __syncthreads();
    if (m < OHDIM) {
        float s = 0.0f;
        #pragma unroll
        for (int fh = 0; fh < FHW; fh++)
            #pragma unroll
            for (int fw = 0; fw < FHW; fw++) {
                float v = simg[fh*HIMG + m + fw];
                s += v*v;
            }
        spsq[m] = s;
        smean[m] = 0.0f;
    }
    __syncthreads();

    float v = pvar[0];
    const float* zr = &sZ[m*LDIM];
    float zq = szsq[m];
    float al = salpha[m];
    for (int ow = 0; ow < OHDIM; ow++) {
        float dot = 0.0f;
        #pragma unroll
        for (int fh = 0; fh < FHW; fh++)
            #pragma unroll
            for (int fw = 0; fw < FHW; fw++)
                dot += zr[fh*FHW + fw] * simg[fh*HIMG + ow + fw];
        float d2 = zq + spsq[ow] - 2.0f*dot;
        d2 = fmaxf(d2, 0.0f);
        float k = v * expf(-0.5f * d2);
        int p = oh*OHDIM + ow;
        g_K[((size_t)(p*NIMG + n))*MDIM + m] = k;
        float pm = k * al;
        #pragma unroll
        for (int off = 16; off > 0; off >>= 1)
            pm += __shfl_down_sync(0xffffffffu, pm, off);
        if ((m & 31) == 0) atomicAdd(&smean[ow], pm);
    }
    __syncthreads();
    if (m < OHDIM) out_mean[n*PDIM + oh*OHDIM + m] = smean[m];
}

// ---------------- quadratic form: var = variance + k^T C k ----------------
// one block per p (64 rows = all n), 256 threads, smem-tiled K rows
#define SKSTRIDE 385
__global__ __launch_bounds__(256) void quad_kernel(const float* __restrict__ pvar,
                                                   float* __restrict__ out_var) {
    extern __shared__ float sm[];
    float* sK   = sm;                    // [64][385]
    float* svar = sm + 64*SKSTRIDE;      // [64]
    int p = blockIdx.x;
    int tid = threadIdx.x;
    size_t base = (size_t)p * 64 * MDIM;

    for (int idx = tid; idx < 64*MDIM; idx += 256) {
        int r = idx / MDIM, c = idx - r*MDIM;
        sK[r*SKSTRIDE + c] = g_K[base + idx];
    }
    if (tid < 64) svar[tid] = 0.0f;
    __syncthreads();

    int tx = tid & 15, ty = tid >> 4;
    int r0 = ty * 4;
    for (int jc = 0; jc < 6; jc++) {
        int c0 = jc*64 + tx*4;
        float acc[4][4];
        #pragma unroll
        for (int r = 0; r < 4; r++)
            #pragma unroll
            for (int c = 0; c < 4; c++) acc[r][c] = 0.0f;

        #pragma unroll 4
        for (int kk = 0; kk < MDIM; kk++) {
            float4 cv = *reinterpret_cast<const float4*>(&g_Cm[kk*MDIM + c0]);
            float k0 = sK[(r0+0)*SKSTRIDE + kk];
            float k1 = sK[(r0+1)*SKSTRIDE + kk];
            float k2 = sK[(r0+2)*SKSTRIDE + kk];
            float k3 = sK[(r0+3)*SKSTRIDE + kk];
            acc[0][0] += k0*cv.x; acc[0][1] += k0*cv.y; acc[0][2] += k0*cv.z; acc[0][3] += k0*cv.w;
            acc[1][0] += k1*cv.x; acc[1][1] += k1*cv.y; acc[1][2] += k1*cv.z; acc[1][3] += k1*cv.w;
            acc[2][0] += k2*cv.x; acc[2][1] += k2*cv.y; acc[2][2] += k2*cv.z; acc[2][3] += k2*cv.w;
            acc[3][0] += k3*cv.x; acc[3][1] += k3*cv.y; acc[3][2] += k3*cv.z; acc[3][3] += k3*cv.w;
        }
        #pragma unroll
        for (int r = 0; r < 4; r++) {
            float s = acc[r][0]*sK[(r0+r)*SKSTRIDE + c0 + 0]
                    + acc[r][1]*sK[(r0+r)*SKSTRIDE + c0 + 1]
                    + acc[r][2]*sK[(r0+r)*SKSTRIDE + c0 + 2]
                    + acc[r][3]*sK[(r0+r)*SKSTRIDE + c0 + 3];
            atomicAdd(&svar[r0 + r], s);
        }
    }
    __syncthreads();
    if (tid < 64) {
        // row index within block = n;   i = p*64 + n
        out_var[(size_t)tid*PDIM + p] = pvar[0] + svar[tid];
    }
}

// ---------------- host launch ----------------
extern "C" void kernel_launch(void* const* d_in, const int* in_sizes, int n_in,
                              void* d_out, int out_size) {
    const float* X    = (const float*)d_in[0];
    const float* Z    = (const float*)d_in[1];
    const float* qmu  = (const float*)d_in[2];
    const float* qsq  = (const float*)d_in[3];
    const float* pvar = (const float*)d_in[4];
    const float* plen = (const float*)d_in[5];
    float* out = (float*)d_out;
    float* out_mean = out;
    float* out_var  = out + (size_t)NIMG*PDIM;

    float *pKuu, *pW, *pW2, *pR, *pLs, *pqS, *pT, *pCm;
    cudaGetSymbolAddress((void**)&pKuu, g_Kuu);
    cudaGetSymbolAddress((void**)&pW,   g_W);
    cudaGetSymbolAddress((void**)&pW2,  g_W2);
    cudaGetSymbolAddress((void**)&pR,   g_R);
    cudaGetSymbolAddress((void**)&pLs,  g_Ls);
    cudaGetSymbolAddress((void**)&pqS,  g_qS);
    cudaGetSymbolAddress((void**)&pT,   g_T);
    cudaGetSymbolAddress((void**)&pCm,  g_Cm);

    prep_kernel<<<64, 256>>>(X, Z, qsq, pvar, plen);
    zsq_kernel<<<2, 256>>>();
    kuu_kernel<<<(MDIM*MDIM + 255)/256, 256>>>(pvar);

    dim3 ggrid(12, 12);
    // Newton-Schulz: W <- W(2I - Kuu W), 3 iterations
    gemm384<<<ggrid, 256>>>(pKuu, pW,  pR,  pKuu, 1, 0);
    gemm384<<<ggrid, 256>>>(pW,   pR,  pW2, pKuu, 0, 0);
    gemm384<<<ggrid, 256>>>(pKuu, pW2, pR,  pKuu, 1, 0);
    gemm384<<<ggrid, 256>>>(pW2,  pR,  pW,  pKuu, 0, 0);
    gemm384<<<ggrid, 256>>>(pKuu, pW,  pR,  pKuu, 1, 0);
    gemm384<<<ggrid, 256>>>(pW,   pR,  pW2, pKuu, 0, 0);
    float* pWf = pW2;

    // qS = Ls Ls^T ; T = W qS ; C = T W - W
    gemm384<<<ggrid, 256>>>(pLs, pLs, pqS, pKuu, 0, 1);
    gemm384<<<ggrid, 256>>>(pWf, pqS, pT,  pKuu, 0, 0);
    gemm384<<<ggrid, 256>>>(pT,  pWf, pCm, pWf,  2, 0);

    alpha_kernel<<<3, 128>>>(pWf, qmu);

    dim3 kgrid(OHDIM, NIMG);
    kuf_kernel<<<kgrid, 384>>>(pvar, out_mean);

    int smem_bytes = (64*SKSTRIDE + 64) * (int)sizeof(float);
    cudaFuncSetAttribute(quad_kernel, cudaFuncAttributeMaxDynamicSharedMemorySize, smem_bytes);
    quad_kernel<<<PDIM, 256, smem_bytes>>>(pvar, out_var);
}